// round 13
// baseline (speedup 1.0000x reference)
#include <cuda_runtime.h>
#include <cuda_bf16.h>
#include <cuda_fp16.h>
#include <math.h>
#include <stdint.h>

// Problem constants
#define BB 8
#define CC 256
#define HH 128
#define WW 128
#define HP 64
#define WP 64
#define NC8 32
#define CE  240
#define FIN 496

// -------- scratch (device globals; no allocation allowed) --------
__device__ float g_A[3][BB][CC][WW];
__device__ float g_k[BB][NC8][WP];
__device__ float g_kq[BB][CC][WP];
__device__ float g_kqb[BB][WP];
__device__ float g_e[BB][HP][WP];
__device__ float g_vs[BB][CC][WP];
__device__ float g_G[BB][CE][9][WP];

// channel-last fp16 input planes: [b][y][x][ci(256 padded)] ; 32 uint4 per pixel
__device__ uint4 g_X4[(size_t)BB * 128 * 128 * 32];
// weight tiles: 36 (9 shifts x 4 ci-blocks) x [n=256][k=64] fp16 row-major
__device__ uint4 g_W4[36 * 2048];

// ================= helpers =================
__device__ __forceinline__ uint32_t smem_to_u32(const void* p) {
    uint32_t a;
    asm("{ .reg .u64 t; cvta.to.shared.u64 t, %1; cvt.u32.u64 %0, t; }" : "=r"(a) : "l"(p));
    return a;
}
__device__ __forceinline__ void ldsm4(uint32_t* r, uint32_t addr) {
    asm volatile("ldmatrix.sync.aligned.m8n8.x4.shared.b16 {%0,%1,%2,%3}, [%4];"
                 : "=r"(r[0]), "=r"(r[1]), "=r"(r[2]), "=r"(r[3]) : "r"(addr));
}
__device__ __forceinline__ void mma_fp16(float* c, const uint32_t* a, const uint32_t* b) {
    asm volatile(
        "mma.sync.aligned.m16n8k16.row.col.f32.f16.f16.f32 "
        "{%0,%1,%2,%3}, {%4,%5,%6,%7}, {%8,%9}, {%0,%1,%2,%3};"
        : "+f"(c[0]), "+f"(c[1]), "+f"(c[2]), "+f"(c[3])
        : "r"(a[0]), "r"(a[1]), "r"(a[2]), "r"(a[3]), "r"(b[0]), "r"(b[1]));
}
__device__ __forceinline__ void cpasync16(uint32_t dst, const void* src, uint32_t sz) {
    asm volatile("cp.async.cg.shared.global [%0], [%1], 16, %2;"
                 :: "r"(dst), "l"(src), "r"(sz) : "memory");
}
#define CP_COMMIT() asm volatile("cp.async.commit_group;" ::: "memory")
#define CP_WAIT0()  asm volatile("cp.async.wait_group 0;" ::: "memory")

// ================= small kernels =================
__global__ void front_reduce_kernel(const float* __restrict__ fx) {
    int c = blockIdx.x, b = blockIdx.y, w = threadIdx.x;
    const float* p = fx + (((size_t)b * CC + c) * HH) * WW + w;
    float x0 = p[0];
    float xN = p[127 * WW];
    float s = 0.f;
#pragma unroll 8
    for (int h = 0; h < HH; h++) s += p[h * WW];
    g_A[0][b][c][w] = s - xN;
    g_A[1][b][c][w] = s;
    g_A[2][b][c][w] = s - x0;
}

// k: 4-way c-parallel. grid (32 o, 8 b), block 256 = 4 c-subgroups x 64 w'
__global__ void __launch_bounds__(256) k_kernel(const float* __restrict__ kw,
                                                const float* __restrict__ kb) {
    __shared__ float sred[4][64];
    int o = blockIdx.x, b = blockIdx.y;
    int t = threadIdx.x;
    int grp = t >> 6, w = t & 63;
    float acc = 0.f;
#pragma unroll 8
    for (int k = 0; k < 64; k++) {
        int c = grp * 64 + k;
        float m = (g_A[1][b][c][2 * w] + g_A[1][b][c][2 * w + 1]) * (1.f / 256.f);
        acc += kw[o * CC + c] * m;
    }
    sred[grp][w] = acc;
    __syncthreads();
    if (grp == 0)
        g_k[b][o][w] = sred[0][w] + sred[1][w] + sred[2][w] + sred[3][w] + kb[o];
}

__global__ void kq_kernel(const float* __restrict__ qw, const float* __restrict__ qb) {
    int tid = blockIdx.x * 256 + threadIdx.x;
    int w = tid & 63, c = (tid >> 6) & 255, b = tid >> 14;
    float acc = 0.f, accb = 0.f;
#pragma unroll 8
    for (int o = 0; o < NC8; o++) {
        float kk = g_k[b][o][w];
        acc  += kk * qw[o * CC + c];
        accb += kk * qb[o];
    }
    g_kq[b][c][w] = acc;
    if (c == 0) g_kqb[b][w] = accb;
}

// e fused with 2x2 avgpool of bev. grid (HP, BB), block 256 = 4 c-subgroups x 64 w'
__global__ void __launch_bounds__(256) e_fused_kernel(const float* __restrict__ bev) {
    __shared__ float sred[4][64];
    int h = blockIdx.x, b = blockIdx.y;
    int t = threadIdx.x;
    int grp = t >> 6, w = t & 63;
    float acc = 0.f;
#pragma unroll 4
    for (int k = 0; k < 64; k++) {
        int c = grp * 64 + k;
        const float2* r0 = (const float2*)(bev + (((size_t)b * CC + c) * HH + 2 * h) * WW);
        const float2* r1 = (const float2*)(bev + (((size_t)b * CC + c) * HH + 2 * h + 1) * WW);
        float2 a = r0[w], d = r1[w];
        float m = 0.25f * (a.x + a.y + d.x + d.y);
        acc += g_kq[b][c][w] * m;
    }
    sred[grp][w] = acc;
    __syncthreads();
    if (grp == 0)
        g_e[b][h][w] = sred[0][w] + sred[1][w] + sred[2][w] + sred[3][w] + g_kqb[b][w];
}

__global__ void enorm_kernel() {
    int w = blockIdx.x, b = blockIdx.y, h = threadIdx.x;
    float v = g_e[b][h][w];
    float s = v * v;
#pragma unroll
    for (int off = 16; off; off >>= 1) s += __shfl_xor_sync(0xffffffffu, s, off);
    __shared__ float sh[2];
    if ((h & 31) == 0) sh[h >> 5] = s;
    __syncthreads();
    float tot = sh[0] + sh[1];
    g_e[b][h][w] = v * rsqrtf(tot);
}

// vsum: 4-way c-parallel. grid (32 cg, 8 b), block 256 = 4 c-subgroups x 64 w'
__global__ void __launch_bounds__(256) vsum_kernel(const float* __restrict__ vw,
                                                   const float* __restrict__ vb) {
    __shared__ float sA[4][3][132];
    __shared__ float sW[4][8][9];
    __shared__ float sred[4][8][64];
    int b = blockIdx.y, cg = blockIdx.x;
    int t = threadIdx.x;
    int grp = t >> 6, w = t & 63;
    float acc[8];
#pragma unroll
    for (int j = 0; j < 8; j++) acc[j] = 0.f;

    for (int k = 0; k < 64; k++) {
        int ci = 4 * k + grp;
        __syncthreads();
        for (int i = w; i < 390; i += 64) {
            int arr = i / 130, u = i % 130;
            float v = 0.f;
            if (u >= 1 && u <= 128) v = g_A[arr][b][ci][u - 1];
            sA[grp][arr][u] = v;
        }
        for (int i = w; i < 72; i += 64) {
            int j = i / 9, kk = i % 9;
            sW[grp][j][kk] = vw[((size_t)(cg * 8 + j) * CC + ci) * 9 + kk];
        }
        __syncthreads();
#pragma unroll
        for (int sub = 0; sub < 2; sub++) {
            int wf = 2 * w + sub;
            float a[3][3];
#pragma unroll
            for (int dy = 0; dy < 3; dy++)
#pragma unroll
                for (int dx = 0; dx < 3; dx++) a[dy][dx] = sA[grp][dy][wf + dx];
#pragma unroll
            for (int j = 0; j < 8; j++) {
                float s = acc[j];
#pragma unroll
                for (int dy = 0; dy < 3; dy++)
#pragma unroll
                    for (int dx = 0; dx < 3; dx++) s += sW[grp][j][dy * 3 + dx] * a[dy][dx];
                acc[j] = s;
            }
        }
    }
    __syncthreads();
#pragma unroll
    for (int j = 0; j < 8; j++) sred[grp][j][w] = acc[j];
    __syncthreads();
    if (grp == 0) {
#pragma unroll
        for (int j = 0; j < 8; j++) {
            float tot = sred[0][j][w] + sred[1][j][w] + sred[2][j][w] + sred[3][j][w];
            g_vs[b][cg * 8 + j][w] = 0.25f * tot + 64.f * vb[cg * 8 + j];
        }
    }
}

// G: stage contiguous 2304-float weight block in smem. grid (CE, BB), 64 threads
__global__ void G_kernel(const float* __restrict__ fw) {
    __shared__ float sw[2304];
    int b = blockIdx.y, o = blockIdx.x, t = threadIdx.x;
    const float* wbase = fw + ((size_t)o * FIN + 240) * 9;
    for (int i = t; i < 2304; i += 64) sw[i] = wbase[i];
    __syncthreads();
    float acc[9];
#pragma unroll
    for (int j = 0; j < 9; j++) acc[j] = 0.f;
    for (int c = 0; c < CC; c++) {
        float v = g_vs[b][c][t];
#pragma unroll
        for (int j = 0; j < 9; j++) acc[j] += sw[c * 9 + j] * v;
    }
#pragma unroll
    for (int j = 0; j < 9; j++) g_G[b][o][j][t] = acc[j];
}

__global__ void copy16_kernel(const float* __restrict__ bev, float* __restrict__ out) {
    int idx = blockIdx.x * 256 + threadIdx.x;
    int b = idx / (16 * 4096);
    int r = idx - b * (16 * 4096);
    size_t off = (size_t)b * (CC * 4096) + r;
    ((float4*)out)[off] = ((const float4*)bev)[off];
}

// ================= precompute kernels =================
__global__ void __launch_bounds__(256) split_kernel(const float* __restrict__ bev) {
    __shared__ float sb[64][129];
    int y = blockIdx.x, b = blockIdx.y, t = threadIdx.x;
    for (int cb = 0; cb < 4; cb++) {
        __syncthreads();
        for (int i = t; i < 64 * 128; i += 256) {
            int ci = i >> 7, x = i & 127;
            int ch = cb * 64 + ci;
            float v = 0.f;
            if (ch < 240)
                v = bev[(((size_t)b * CC + 16 + ch) * HH + y) * WW + x];
            sb[ci][x] = v;
        }
        __syncthreads();
        for (int i = t; i < 128 * 32; i += 256) {
            int x = i >> 5, cp = i & 31;
            __half h0 = __float2half(sb[2 * cp][x]);
            __half h1 = __float2half(sb[2 * cp + 1][x]);
            uint32_t hp = ((uint32_t)__half_as_ushort(h1) << 16) | __half_as_ushort(h0);
            size_t base = (((size_t)b * 128 + y) * 128 + x) * 128 + cb * 32 + cp;
            ((uint32_t*)g_X4)[base] = hp;
        }
    }
}

__global__ void wbuild_kernel(const float* __restrict__ fw) {
    int tile = blockIdx.y;
    int s = tile >> 2, cib = tile & 3;
    int idx = blockIdx.x * 256 + threadIdx.x;
    int n = idx >> 6, k = idx & 63;
    int ci = cib * 64 + k;
    float v = 0.f;
    if (n < 240 && ci < 240) v = fw[((size_t)n * FIN + ci) * 9 + s];
    ((__half*)(g_W4 + (size_t)tile * 2048))[idx] = __float2half(v);
}

// ================= HMMA conv kernel =================
// CTA = one (b, y) row: M=128 px, N=256 o. 512 threads = 16 warps, warp tile 32M x 64N.
// K = 9 shifts x 2 ci-halves of 128 = 18 chunks (K=128 per chunk).
#define NCHUNK 18
#define ROWB   272                     // 128 ci x 2B = 256B + 16B pad
#define ABYTES (128 * ROWB)            // 34816
#define BUFSZ  (ABYTES + 256 * ROWB)   // 104448
#define CONV_SMEM (2 * BUFSZ)          // 208896

__device__ __forceinline__ void load_chunk(int c, uint32_t sbuf, int t, int b, int y) {
    int s = c >> 1, cibp = c & 1;
    int dy = s / 3, dx = s % 3;
    // two 64-ci weight tiles feed this 128-ci chunk
    const uint4* Wsrc0 = g_W4 + (size_t)(s * 4 + cibp * 2) * 2048;
    const uint4* Wsrc1 = Wsrc0 + 2048;

    int yy = y + dy - 1;
    bool yok = ((unsigned)yy < 128u);
    const uint4* xrow = g_X4 + (((size_t)b * 128 + (yok ? yy : 0)) * 128) * 32 + cibp * 16;
    // A: 128 rows x 16 uint4 = 2048; 4 per thread
#pragma unroll
    for (int r = 0; r < 4; r++) {
        int i = t + r * 512;
        int m = i >> 4, j = i & 15;
        int xx = m + dx - 1;
        bool ok = yok && ((unsigned)xx < 128u);
        const uint4* src = xrow + (size_t)(ok ? xx : 0) * 32 + j;
        cpasync16(sbuf + m * ROWB + j * 16, src, ok ? 16u : 0u);
    }
    // B: 256 rows x 16 uint4 = 4096; 8 per thread. j<8 from tile0, j>=8 from tile1.
#pragma unroll
    for (int r = 0; r < 8; r++) {
        int i = t + r * 512;
        int n = i >> 4, j = i & 15;
        const uint4* src = (j < 8) ? (Wsrc0 + n * 8 + j) : (Wsrc1 + n * 8 + (j - 8));
        cpasync16(sbuf + ABYTES + n * ROWB + j * 16, src, 16u);
    }
    CP_COMMIT();
}

__device__ __forceinline__ void do_ks(int ks, uint32_t aBase, uint32_t bBase,
                                      float acc[2][8][4], int ntMax, int nnMax) {
    uint32_t a[2][4];
    ldsm4(a[0], aBase + ks * 32);
    ldsm4(a[1], aBase + 16 * ROWB + ks * 32);
    uint32_t bf[4][4];
#pragma unroll
    for (int nt = 0; nt < 4; nt++)
        if (nt < ntMax) ldsm4(bf[nt], bBase + nt * 16 * ROWB + ks * 32);
#pragma unroll
    for (int mt = 0; mt < 2; mt++)
#pragma unroll
        for (int nn = 0; nn < 8; nn++)
            if (nn < nnMax) mma_fp16(acc[mt][nn], a[mt], &bf[nn >> 1][(nn & 1) * 2]);
}

__global__ void __launch_bounds__(512, 1)
mma_conv_kernel(const float* __restrict__ fb, float* __restrict__ out) {
    extern __shared__ uint4 dsm[];
    uint32_t sb = smem_to_u32(dsm);

    int t = threadIdx.x;
    int l = t & 31, wid = t >> 5;
    int y = blockIdx.x, b = blockIdx.y;
    int m0 = (wid & 3) * 32;
    int n0 = (wid >> 2) * 64;
    const int nnMax = (n0 == 192) ? 6 : 8;
    const int ntMax = (n0 == 192) ? 3 : 4;

    float acc[2][8][4];
#pragma unroll
    for (int i = 0; i < 2; i++)
#pragma unroll
        for (int j = 0; j < 8; j++)
#pragma unroll
            for (int k = 0; k < 4; k++) acc[i][j][k] = 0.f;

    uint32_t aOff = (uint32_t)(m0 + (l & 15)) * ROWB + (l >> 4) * 16;
    uint32_t bOff = ABYTES + (uint32_t)(n0 + (l & 7) + ((l >> 4) << 3)) * ROWB
                    + ((l >> 3) & 1) * 16;

    load_chunk(0, sb, t, b, y);
    CP_WAIT0();
    __syncthreads();

    for (int c = 0; c < NCHUNK; c++) {
        uint32_t buf = sb + (c & 1) * BUFSZ;
        if (c + 1 < NCHUNK) load_chunk(c + 1, sb + ((c + 1) & 1) * BUFSZ, t, b, y);

        uint32_t aBase = buf + aOff;
        uint32_t bBase = buf + bOff;
        // cibp==1 covers ci 128..255; ci 240..255 (k 112..127 = ks 7) are zero padding
        int ksMax = (c & 1) ? 7 : 8;
#pragma unroll
        for (int ks = 0; ks < 8; ks++)
            if (ks < ksMax) do_ks(ks, aBase, bBase, acc, ntMax, nnMax);

        if (c + 1 < NCHUNK) CP_WAIT0();
        __syncthreads();
    }

    // Epilogue: bias + factorized T contribution, scattered stores
    int g = l >> 2, tq = l & 3;
    float* outb = out + ((size_t)b * CC + 16) * (HH * WW) + y * WW;
#pragma unroll
    for (int mt = 0; mt < 2; mt++) {
        int xA = m0 + mt * 16 + g;
        int xB = xA + 8;
#pragma unroll
        for (int nn = 0; nn < 8; nn++) {
            int o0 = n0 + nn * 8 + 2 * tq;
            if (o0 >= 240) continue;
            float b0 = fb[o0], b1 = fb[o0 + 1];
#pragma unroll
            for (int half = 0; half < 2; half++) {
                int x = half ? xB : xA;
                float v0 = acc[mt][nn][half * 2 + 0] + b0;
                float v1 = acc[mt][nn][half * 2 + 1] + b1;
#pragma unroll
                for (int dy2 = 0; dy2 < 3; dy2++) {
                    int yy = y + dy2 - 1;
                    if ((unsigned)yy >= 128u) continue;
                    int hh = yy >> 1;
#pragma unroll
                    for (int dx2 = 0; dx2 < 3; dx2++) {
                        int xx = x + dx2 - 1;
                        if ((unsigned)xx >= 128u) continue;
                        int ww = xx >> 1;
                        float ev = g_e[b][hh][ww];
                        v0 += ev * g_G[b][o0][dy2 * 3 + dx2][ww];
                        v1 += ev * g_G[b][o0 + 1][dy2 * 3 + dx2][ww];
                    }
                }
                outb[(size_t)o0 * (HH * WW) + x] = v0;
                outb[(size_t)(o0 + 1) * (HH * WW) + x] = v1;
            }
        }
    }
}

// ---------------------------------------------------------------
extern "C" void kernel_launch(void* const* d_in, const int* in_sizes, int n_in,
                              void* d_out, int out_size) {
    const float* front = (const float*)d_in[0];
    const float* bev   = (const float*)d_in[1];
    const float* qw    = (const float*)d_in[2];
    const float* qb    = (const float*)d_in[3];
    const float* kw    = (const float*)d_in[4];
    const float* kb    = (const float*)d_in[5];
    const float* vw    = (const float*)d_in[6];
    const float* vb    = (const float*)d_in[7];
    const float* fw    = (const float*)d_in[8];
    const float* fb    = (const float*)d_in[9];
    float* out = (float*)d_out;

    cudaFuncSetAttribute(mma_conv_kernel,
                         cudaFuncAttributeMaxDynamicSharedMemorySize, CONV_SMEM);

    split_kernel<<<dim3(128, BB), 256>>>(bev);
    wbuild_kernel<<<dim3(64, 36), 256>>>(fw);
    front_reduce_kernel<<<dim3(CC, BB), 128>>>(front);
    k_kernel<<<dim3(NC8, BB), 256>>>(kw, kb);
    kq_kernel<<<512, 256>>>(qw, qb);
    e_fused_kernel<<<dim3(HP, BB), 256>>>(bev);
    enorm_kernel<<<dim3(WP, BB), HP>>>();
    vsum_kernel<<<dim3(32, BB), 256>>>(vw, vb);
    G_kernel<<<dim3(CE, BB), 64>>>(fw);
    copy16_kernel<<<2048, 256>>>(bev, out);
    mma_conv_kernel<<<dim3(128, BB), 512, CONV_SMEM>>>(fb, out);
}

// round 14
// speedup vs baseline: 1.0725x; 1.0725x over previous
#include <cuda_runtime.h>
#include <cuda_bf16.h>
#include <cuda_fp16.h>
#include <math.h>
#include <stdint.h>

// Problem constants
#define BB 8
#define CC 256
#define HH 128
#define WW 128
#define HP 64
#define WP 64
#define NC8 32
#define CE  240
#define FIN 496

// -------- scratch (device globals; no allocation allowed) --------
__device__ float g_A[3][BB][CC][WW];
__device__ float g_k[BB][NC8][WP];
__device__ float g_kq[BB][CC][WP];
__device__ float g_kqb[BB][WP];
__device__ float g_e[BB][HP][WP];
__device__ float g_vs[BB][CC][WP];
__device__ float g_G[BB][CE][9][WP];

// channel-last fp16 input planes: [b][y][x][ci(256 padded)] ; 32 uint4 per pixel
__device__ uint4 g_X4[(size_t)BB * 128 * 128 * 32];
// weight tiles: 36 (9 shifts x 4 ci-blocks) x [n=256][k=64] fp16 row-major
__device__ uint4 g_W4[36 * 2048];

// ================= helpers =================
__device__ __forceinline__ uint32_t smem_to_u32(const void* p) {
    uint32_t a;
    asm("{ .reg .u64 t; cvta.to.shared.u64 t, %1; cvt.u32.u64 %0, t; }" : "=r"(a) : "l"(p));
    return a;
}
__device__ __forceinline__ void ldsm4(uint32_t* r, uint32_t addr) {
    asm volatile("ldmatrix.sync.aligned.m8n8.x4.shared.b16 {%0,%1,%2,%3}, [%4];"
                 : "=r"(r[0]), "=r"(r[1]), "=r"(r[2]), "=r"(r[3]) : "r"(addr));
}
__device__ __forceinline__ void mma_fp16(float* c, const uint32_t* a, const uint32_t* b) {
    asm volatile(
        "mma.sync.aligned.m16n8k16.row.col.f32.f16.f16.f32 "
        "{%0,%1,%2,%3}, {%4,%5,%6,%7}, {%8,%9}, {%0,%1,%2,%3};"
        : "+f"(c[0]), "+f"(c[1]), "+f"(c[2]), "+f"(c[3])
        : "r"(a[0]), "r"(a[1]), "r"(a[2]), "r"(a[3]), "r"(b[0]), "r"(b[1]));
}
__device__ __forceinline__ void cpasync16(uint32_t dst, const void* src, uint32_t sz) {
    asm volatile("cp.async.cg.shared.global [%0], [%1], 16, %2;"
                 :: "r"(dst), "l"(src), "r"(sz) : "memory");
}
#define CP_COMMIT() asm volatile("cp.async.commit_group;" ::: "memory")
#define CP_WAIT0()  asm volatile("cp.async.wait_group 0;" ::: "memory")

// ================= small kernels =================
__global__ void front_reduce_kernel(const float* __restrict__ fx) {
    int c = blockIdx.x, b = blockIdx.y, w = threadIdx.x;
    const float* p = fx + (((size_t)b * CC + c) * HH) * WW + w;
    float x0 = p[0];
    float xN = p[127 * WW];
    float s = 0.f;
#pragma unroll 8
    for (int h = 0; h < HH; h++) s += p[h * WW];
    g_A[0][b][c][w] = s - xN;
    g_A[1][b][c][w] = s;
    g_A[2][b][c][w] = s - x0;
}

// k: 4-way c-parallel. grid (32 o, 8 b), block 256 = 4 c-subgroups x 64 w'
__global__ void __launch_bounds__(256) k_kernel(const float* __restrict__ kw,
                                                const float* __restrict__ kb) {
    __shared__ float sred[4][64];
    int o = blockIdx.x, b = blockIdx.y;
    int t = threadIdx.x;
    int grp = t >> 6, w = t & 63;
    float acc = 0.f;
#pragma unroll 8
    for (int k = 0; k < 64; k++) {
        int c = grp * 64 + k;
        float m = (g_A[1][b][c][2 * w] + g_A[1][b][c][2 * w + 1]) * (1.f / 256.f);
        acc += kw[o * CC + c] * m;
    }
    sred[grp][w] = acc;
    __syncthreads();
    if (grp == 0)
        g_k[b][o][w] = sred[0][w] + sred[1][w] + sred[2][w] + sred[3][w] + kb[o];
}

__global__ void kq_kernel(const float* __restrict__ qw, const float* __restrict__ qb) {
    int tid = blockIdx.x * 256 + threadIdx.x;
    int w = tid & 63, c = (tid >> 6) & 255, b = tid >> 14;
    float acc = 0.f, accb = 0.f;
#pragma unroll 8
    for (int o = 0; o < NC8; o++) {
        float kk = g_k[b][o][w];
        acc  += kk * qw[o * CC + c];
        accb += kk * qb[o];
    }
    g_kq[b][c][w] = acc;
    if (c == 0) g_kqb[b][w] = accb;
}

// e fused with 2x2 avgpool of bev. grid (HP, BB), block 256 = 4 c-subgroups x 64 w'
__global__ void __launch_bounds__(256) e_fused_kernel(const float* __restrict__ bev) {
    __shared__ float sred[4][64];
    int h = blockIdx.x, b = blockIdx.y;
    int t = threadIdx.x;
    int grp = t >> 6, w = t & 63;
    float acc = 0.f;
#pragma unroll 4
    for (int k = 0; k < 64; k++) {
        int c = grp * 64 + k;
        const float2* r0 = (const float2*)(bev + (((size_t)b * CC + c) * HH + 2 * h) * WW);
        const float2* r1 = (const float2*)(bev + (((size_t)b * CC + c) * HH + 2 * h + 1) * WW);
        float2 a = r0[w], d = r1[w];
        float m = 0.25f * (a.x + a.y + d.x + d.y);
        acc += g_kq[b][c][w] * m;
    }
    sred[grp][w] = acc;
    __syncthreads();
    if (grp == 0)
        g_e[b][h][w] = sred[0][w] + sred[1][w] + sred[2][w] + sred[3][w] + g_kqb[b][w];
}

__global__ void enorm_kernel() {
    int w = blockIdx.x, b = blockIdx.y, h = threadIdx.x;
    float v = g_e[b][h][w];
    float s = v * v;
#pragma unroll
    for (int off = 16; off; off >>= 1) s += __shfl_xor_sync(0xffffffffu, s, off);
    __shared__ float sh[2];
    if ((h & 31) == 0) sh[h >> 5] = s;
    __syncthreads();
    float tot = sh[0] + sh[1];
    g_e[b][h][w] = v * rsqrtf(tot);
}

// vsum: 4-way c-parallel. grid (32 cg, 8 b), block 256 = 4 c-subgroups x 64 w'
__global__ void __launch_bounds__(256) vsum_kernel(const float* __restrict__ vw,
                                                   const float* __restrict__ vb) {
    __shared__ float sA[4][3][132];
    __shared__ float sW[4][8][9];
    __shared__ float sred[4][8][64];
    int b = blockIdx.y, cg = blockIdx.x;
    int t = threadIdx.x;
    int grp = t >> 6, w = t & 63;
    float acc[8];
#pragma unroll
    for (int j = 0; j < 8; j++) acc[j] = 0.f;

    for (int k = 0; k < 64; k++) {
        int ci = 4 * k + grp;
        __syncthreads();
        for (int i = w; i < 390; i += 64) {
            int arr = i / 130, u = i % 130;
            float v = 0.f;
            if (u >= 1 && u <= 128) v = g_A[arr][b][ci][u - 1];
            sA[grp][arr][u] = v;
        }
        for (int i = w; i < 72; i += 64) {
            int j = i / 9, kk = i % 9;
            sW[grp][j][kk] = vw[((size_t)(cg * 8 + j) * CC + ci) * 9 + kk];
        }
        __syncthreads();
#pragma unroll
        for (int sub = 0; sub < 2; sub++) {
            int wf = 2 * w + sub;
            float a[3][3];
#pragma unroll
            for (int dy = 0; dy < 3; dy++)
#pragma unroll
                for (int dx = 0; dx < 3; dx++) a[dy][dx] = sA[grp][dy][wf + dx];
#pragma unroll
            for (int j = 0; j < 8; j++) {
                float s = acc[j];
#pragma unroll
                for (int dy = 0; dy < 3; dy++)
#pragma unroll
                    for (int dx = 0; dx < 3; dx++) s += sW[grp][j][dy * 3 + dx] * a[dy][dx];
                acc[j] = s;
            }
        }
    }
    __syncthreads();
#pragma unroll
    for (int j = 0; j < 8; j++) sred[grp][j][w] = acc[j];
    __syncthreads();
    if (grp == 0) {
#pragma unroll
        for (int j = 0; j < 8; j++) {
            float tot = sred[0][j][w] + sred[1][j][w] + sred[2][j][w] + sred[3][j][w];
            g_vs[b][cg * 8 + j][w] = 0.25f * tot + 64.f * vb[cg * 8 + j];
        }
    }
}

// G: stage contiguous 2304-float weight block in smem. grid (CE, BB), 64 threads
__global__ void G_kernel(const float* __restrict__ fw) {
    __shared__ float sw[2304];
    int b = blockIdx.y, o = blockIdx.x, t = threadIdx.x;
    const float* wbase = fw + ((size_t)o * FIN + 240) * 9;
    for (int i = t; i < 2304; i += 64) sw[i] = wbase[i];
    __syncthreads();
    float acc[9];
#pragma unroll
    for (int j = 0; j < 9; j++) acc[j] = 0.f;
    for (int c = 0; c < CC; c++) {
        float v = g_vs[b][c][t];
#pragma unroll
        for (int j = 0; j < 9; j++) acc[j] += sw[c * 9 + j] * v;
    }
#pragma unroll
    for (int j = 0; j < 9; j++) g_G[b][o][j][t] = acc[j];
}

__global__ void copy16_kernel(const float* __restrict__ bev, float* __restrict__ out) {
    int idx = blockIdx.x * 256 + threadIdx.x;
    int b = idx / (16 * 4096);
    int r = idx - b * (16 * 4096);
    size_t off = (size_t)b * (CC * 4096) + r;
    ((float4*)out)[off] = ((const float4*)bev)[off];
}

// ================= precompute kernels =================
__global__ void __launch_bounds__(256) split_kernel(const float* __restrict__ bev) {
    __shared__ float sb[64][129];
    int y = blockIdx.x, b = blockIdx.y, t = threadIdx.x;
    for (int cb = 0; cb < 4; cb++) {
        __syncthreads();
        for (int i = t; i < 64 * 128; i += 256) {
            int ci = i >> 7, x = i & 127;
            int ch = cb * 64 + ci;
            float v = 0.f;
            if (ch < 240)
                v = bev[(((size_t)b * CC + 16 + ch) * HH + y) * WW + x];
            sb[ci][x] = v;
        }
        __syncthreads();
        for (int i = t; i < 128 * 32; i += 256) {
            int x = i >> 5, cp = i & 31;
            __half h0 = __float2half(sb[2 * cp][x]);
            __half h1 = __float2half(sb[2 * cp + 1][x]);
            uint32_t hp = ((uint32_t)__half_as_ushort(h1) << 16) | __half_as_ushort(h0);
            size_t base = (((size_t)b * 128 + y) * 128 + x) * 128 + cb * 32 + cp;
            ((uint32_t*)g_X4)[base] = hp;
        }
    }
}

__global__ void wbuild_kernel(const float* __restrict__ fw) {
    int tile = blockIdx.y;
    int s = tile >> 2, cib = tile & 3;
    int idx = blockIdx.x * 256 + threadIdx.x;
    int n = idx >> 6, k = idx & 63;
    int ci = cib * 64 + k;
    float v = 0.f;
    if (n < 240 && ci < 240) v = fw[((size_t)n * FIN + ci) * 9 + s];
    ((__half*)(g_W4 + (size_t)tile * 2048))[idx] = __float2half(v);
}

// ================= HMMA conv kernel (R12 config: NCHUNK=36, ROWB=144) =================
#define NCHUNK 36
#define ROWB   144
#define ABYTES (128 * ROWB)
#define BUFSZ  (ABYTES + 256 * ROWB)
#define CONV_SMEM (2 * BUFSZ)

__device__ __forceinline__ void load_chunk(int c, uint32_t sbuf, int t, int b, int y) {
    int s = c >> 2, cib = c & 3;
    int dy = s / 3, dx = s % 3;
    const uint4* Wsrc = g_W4 + (size_t)c * 2048;

    int yy = y + dy - 1;
    bool yok = ((unsigned)yy < 128u);
    const uint4* xrow = g_X4 + (((size_t)b * 128 + (yok ? yy : 0)) * 128) * 32 + cib * 8;
#pragma unroll
    for (int r = 0; r < 2; r++) {
        int i = t + r * 512;
        int m = i >> 3, j = i & 7;
        int xx = m + dx - 1;
        bool ok = yok && ((unsigned)xx < 128u);
        const uint4* src = xrow + (size_t)(ok ? xx : 0) * 32 + j;
        cpasync16(sbuf + m * ROWB + j * 16, src, ok ? 16u : 0u);
    }
#pragma unroll
    for (int r = 0; r < 4; r++) {
        int i = t + r * 512;
        int n = i >> 3, j = i & 7;
        cpasync16(sbuf + ABYTES + n * ROWB + j * 16, Wsrc + n * 8 + j, 16u);
    }
    CP_COMMIT();
}

__device__ __forceinline__ void do_ks(int ks, uint32_t aBase, uint32_t bBase,
                                      float acc[2][8][4], int ntMax, int nnMax) {
    uint32_t a[2][4];
    ldsm4(a[0], aBase + ks * 32);
    ldsm4(a[1], aBase + 16 * ROWB + ks * 32);
    uint32_t bf[4][4];
#pragma unroll
    for (int nt = 0; nt < 4; nt++)
        if (nt < ntMax) ldsm4(bf[nt], bBase + nt * 16 * ROWB + ks * 32);
#pragma unroll
    for (int mt = 0; mt < 2; mt++)
#pragma unroll
        for (int nn = 0; nn < 8; nn++)
            if (nn < nnMax) mma_fp16(acc[mt][nn], a[mt], &bf[nn >> 1][(nn & 1) * 2]);
}

__global__ void __launch_bounds__(512, 1)
mma_conv_kernel(const float* __restrict__ fb, float* __restrict__ out) {
    extern __shared__ uint4 dsm[];
    uint32_t sb = smem_to_u32(dsm);

    int t = threadIdx.x;
    int l = t & 31, wid = t >> 5;
    int y = blockIdx.x, b = blockIdx.y;
    int m0 = (wid & 3) * 32;
    int n0 = (wid >> 2) * 64;
    const int nnMax = (n0 == 192) ? 6 : 8;
    const int ntMax = (n0 == 192) ? 3 : 4;

    float acc[2][8][4];
#pragma unroll
    for (int i = 0; i < 2; i++)
#pragma unroll
        for (int j = 0; j < 8; j++)
#pragma unroll
            for (int k = 0; k < 4; k++) acc[i][j][k] = 0.f;

    uint32_t aOff = (uint32_t)(m0 + (l & 15)) * ROWB + (l >> 4) * 16;
    uint32_t bOff = ABYTES + (uint32_t)(n0 + (l & 7) + ((l >> 4) << 3)) * ROWB
                    + ((l >> 3) & 1) * 16;

    load_chunk(0, sb, t, b, y);
    CP_WAIT0();
    __syncthreads();

    for (int c = 0; c < NCHUNK; c++) {
        uint32_t buf = sb + (c & 1) * BUFSZ;
        if (c + 1 < NCHUNK) load_chunk(c + 1, sb + ((c + 1) & 1) * BUFSZ, t, b, y);

        uint32_t aBase = buf + aOff;
        uint32_t bBase = buf + bOff;
        int ksMax = ((c & 3) == 3) ? 3 : 4;
#pragma unroll
        for (int ks = 0; ks < 4; ks++)
            if (ks < ksMax) do_ks(ks, aBase, bBase, acc, ntMax, nnMax);

        if (c + 1 < NCHUNK) CP_WAIT0();
        __syncthreads();
    }

    // Epilogue: bias + factorized T contribution, scattered stores
    int g = l >> 2, tq = l & 3;
    float* outb = out + ((size_t)b * CC + 16) * (HH * WW) + y * WW;
#pragma unroll
    for (int mt = 0; mt < 2; mt++) {
        int xA = m0 + mt * 16 + g;
        int xB = xA + 8;
#pragma unroll
        for (int nn = 0; nn < 8; nn++) {
            int o0 = n0 + nn * 8 + 2 * tq;
            if (o0 >= 240) continue;
            float b0 = fb[o0], b1 = fb[o0 + 1];
#pragma unroll
            for (int half = 0; half < 2; half++) {
                int x = half ? xB : xA;
                float v0 = acc[mt][nn][half * 2 + 0] + b0;
                float v1 = acc[mt][nn][half * 2 + 1] + b1;
#pragma unroll
                for (int dy2 = 0; dy2 < 3; dy2++) {
                    int yy = y + dy2 - 1;
                    if ((unsigned)yy >= 128u) continue;
                    int hh = yy >> 1;
#pragma unroll
                    for (int dx2 = 0; dx2 < 3; dx2++) {
                        int xx = x + dx2 - 1;
                        if ((unsigned)xx >= 128u) continue;
                        int ww = xx >> 1;
                        float ev = g_e[b][hh][ww];
                        v0 += ev * g_G[b][o0][dy2 * 3 + dx2][ww];
                        v1 += ev * g_G[b][o0 + 1][dy2 * 3 + dx2][ww];
                    }
                }
                outb[(size_t)o0 * (HH * WW) + x] = v0;
                outb[(size_t)(o0 + 1) * (HH * WW) + x] = v1;
            }
        }
    }
}

// ---------------------------------------------------------------
extern "C" void kernel_launch(void* const* d_in, const int* in_sizes, int n_in,
                              void* d_out, int out_size) {
    const float* front = (const float*)d_in[0];
    const float* bev   = (const float*)d_in[1];
    const float* qw    = (const float*)d_in[2];
    const float* qb    = (const float*)d_in[3];
    const float* kw    = (const float*)d_in[4];
    const float* kb    = (const float*)d_in[5];
    const float* vw    = (const float*)d_in[6];
    const float* vb    = (const float*)d_in[7];
    const float* fw    = (const float*)d_in[8];
    const float* fb    = (const float*)d_in[9];
    float* out = (float*)d_out;

    cudaFuncSetAttribute(mma_conv_kernel,
                         cudaFuncAttributeMaxDynamicSharedMemorySize, CONV_SMEM);

    split_kernel<<<dim3(128, BB), 256>>>(bev);
    wbuild_kernel<<<dim3(64, 36), 256>>>(fw);
    front_reduce_kernel<<<dim3(CC, BB), 128>>>(front);
    k_kernel<<<dim3(NC8, BB), 256>>>(kw, kb);
    kq_kernel<<<512, 256>>>(qw, qb);
    e_fused_kernel<<<dim3(HP, BB), 256>>>(bev);
    enorm_kernel<<<dim3(WP, BB), HP>>>();
    vsum_kernel<<<dim3(32, BB), 256>>>(vw, vb);
    G_kernel<<<dim3(CE, BB), 64>>>(fw);
    copy16_kernel<<<2048, 256>>>(bev, out);
    mma_conv_kernel<<<dim3(128, BB), 512, CONV_SMEM>>>(fb, out);
}

// round 16
// speedup vs baseline: 1.2168x; 1.1346x over previous
#include <cuda_runtime.h>
#include <cuda_bf16.h>
#include <cuda_fp16.h>
#include <math.h>
#include <stdint.h>

// Problem constants
#define BB 8
#define CC 256
#define HH 128
#define WW 128
#define HP 64
#define WP 64
#define NC8 32
#define CE  240
#define FIN 496

// -------- scratch (device globals; no allocation allowed) --------
__device__ float g_A[3][BB][CC][WW];
__device__ float g_k[BB][NC8][WP];
__device__ float g_kq[BB][CC][WP];
__device__ float g_kqb[BB][WP];
__device__ float g_e[BB][HP][WP];
__device__ float g_vs[BB][CC][WP];
__device__ float g_G[BB][CE][9][WP];
__device__ float g_pool[BB][CC][HP][WP];   // 2x2-pooled bev (all 256 ch)

// channel-last fp16 input planes: [b][y][x][ci(256 padded)] ; 32 uint4 per pixel
__device__ uint4 g_X4[(size_t)BB * 128 * 128 * 32];
// weight tiles: 36 (9 shifts x 4 ci-blocks) x [n=256][k=64] fp16 row-major
__device__ uint4 g_W4[36 * 2048];

// ================= helpers =================
__device__ __forceinline__ uint32_t smem_to_u32(const void* p) {
    uint32_t a;
    asm("{ .reg .u64 t; cvta.to.shared.u64 t, %1; cvt.u32.u64 %0, t; }" : "=r"(a) : "l"(p));
    return a;
}
__device__ __forceinline__ void ldsm4(uint32_t* r, uint32_t addr) {
    asm volatile("ldmatrix.sync.aligned.m8n8.x4.shared.b16 {%0,%1,%2,%3}, [%4];"
                 : "=r"(r[0]), "=r"(r[1]), "=r"(r[2]), "=r"(r[3]) : "r"(addr));
}
__device__ __forceinline__ void mma_fp16(float* c, const uint32_t* a, const uint32_t* b) {
    asm volatile(
        "mma.sync.aligned.m16n8k16.row.col.f32.f16.f16.f32 "
        "{%0,%1,%2,%3}, {%4,%5,%6,%7}, {%8,%9}, {%0,%1,%2,%3};"
        : "+f"(c[0]), "+f"(c[1]), "+f"(c[2]), "+f"(c[3])
        : "r"(a[0]), "r"(a[1]), "r"(a[2]), "r"(a[3]), "r"(b[0]), "r"(b[1]));
}
__device__ __forceinline__ void cpasync16(uint32_t dst, const void* src, uint32_t sz) {
    asm volatile("cp.async.cg.shared.global [%0], [%1], 16, %2;"
                 :: "r"(dst), "l"(src), "r"(sz) : "memory");
}
#define CP_COMMIT() asm volatile("cp.async.commit_group;" ::: "memory")
#define CP_WAIT0()  asm volatile("cp.async.wait_group 0;" ::: "memory")

// ================= small kernels =================
__global__ void front_reduce_kernel(const float* __restrict__ fx) {
    int c = blockIdx.x, b = blockIdx.y, w = threadIdx.x;
    const float* p = fx + (((size_t)b * CC + c) * HH) * WW + w;
    float x0 = p[0];
    float xN = p[127 * WW];
    float s = 0.f;
#pragma unroll 8
    for (int h = 0; h < HH; h++) s += p[h * WW];
    g_A[0][b][c][w] = s - xN;
    g_A[1][b][c][w] = s;
    g_A[2][b][c][w] = s - x0;
}

// k: 4-way c-parallel. grid (32 o, 8 b), block 256 = 4 c-subgroups x 64 w'
__global__ void __launch_bounds__(256) k_kernel(const float* __restrict__ kw,
                                                const float* __restrict__ kb) {
    __shared__ float sred[4][64];
    int o = blockIdx.x, b = blockIdx.y;
    int t = threadIdx.x;
    int grp = t >> 6, w = t & 63;
    float acc = 0.f;
#pragma unroll 8
    for (int k = 0; k < 64; k++) {
        int c = grp * 64 + k;
        float m = (g_A[1][b][c][2 * w] + g_A[1][b][c][2 * w + 1]) * (1.f / 256.f);
        acc += kw[o * CC + c] * m;
    }
    sred[grp][w] = acc;
    __syncthreads();
    if (grp == 0)
        g_k[b][o][w] = sred[0][w] + sred[1][w] + sred[2][w] + sred[3][w] + kb[o];
}

__global__ void kq_kernel(const float* __restrict__ qw, const float* __restrict__ qb) {
    int tid = blockIdx.x * 256 + threadIdx.x;
    int w = tid & 63, c = (tid >> 6) & 255, b = tid >> 14;
    float acc = 0.f, accb = 0.f;
#pragma unroll 8
    for (int o = 0; o < NC8; o++) {
        float kk = g_k[b][o][w];
        acc  += kk * qw[o * CC + c];
        accb += kk * qb[o];
    }
    g_kq[b][c][w] = acc;
    if (c == 0) g_kqb[b][w] = accb;
}

// e from precomputed pool. grid (HP, BB), block 256 = 4 c-subgroups x 64 w'
__global__ void __launch_bounds__(256) e_fused_kernel() {
    __shared__ float sred[4][64];
    int h = blockIdx.x, b = blockIdx.y;
    int t = threadIdx.x;
    int grp = t >> 6, w = t & 63;
    float acc = 0.f;
#pragma unroll 4
    for (int k = 0; k < 64; k++) {
        int c = grp * 64 + k;
        acc += g_kq[b][c][w] * g_pool[b][c][h][w];
    }
    sred[grp][w] = acc;
    __syncthreads();
    if (grp == 0)
        g_e[b][h][w] = sred[0][w] + sred[1][w] + sred[2][w] + sred[3][w] + g_kqb[b][w];
}

__global__ void enorm_kernel() {
    int w = blockIdx.x, b = blockIdx.y, h = threadIdx.x;
    float v = g_e[b][h][w];
    float s = v * v;
#pragma unroll
    for (int off = 16; off; off >>= 1) s += __shfl_xor_sync(0xffffffffu, s, off);
    __shared__ float sh[2];
    if ((h & 31) == 0) sh[h >> 5] = s;
    __syncthreads();
    float tot = sh[0] + sh[1];
    g_e[b][h][w] = v * rsqrtf(tot);
}

// vsum: 4-way c-parallel. grid (32 cg, 8 b), block 256 = 4 c-subgroups x 64 w'
__global__ void __launch_bounds__(256) vsum_kernel(const float* __restrict__ vw,
                                                   const float* __restrict__ vb) {
    __shared__ float sA[4][3][132];
    __shared__ float sW[4][8][9];
    __shared__ float sred[4][8][64];
    int b = blockIdx.y, cg = blockIdx.x;
    int t = threadIdx.x;
    int grp = t >> 6, w = t & 63;
    float acc[8];
#pragma unroll
    for (int j = 0; j < 8; j++) acc[j] = 0.f;

    for (int k = 0; k < 64; k++) {
        int ci = 4 * k + grp;
        __syncthreads();
        for (int i = w; i < 390; i += 64) {
            int arr = i / 130, u = i % 130;
            float v = 0.f;
            if (u >= 1 && u <= 128) v = g_A[arr][b][ci][u - 1];
            sA[grp][arr][u] = v;
        }
        for (int i = w; i < 72; i += 64) {
            int j = i / 9, kk = i % 9;
            sW[grp][j][kk] = vw[((size_t)(cg * 8 + j) * CC + ci) * 9 + kk];
        }
        __syncthreads();
#pragma unroll
        for (int sub = 0; sub < 2; sub++) {
            int wf = 2 * w + sub;
            float a[3][3];
#pragma unroll
            for (int dy = 0; dy < 3; dy++)
#pragma unroll
                for (int dx = 0; dx < 3; dx++) a[dy][dx] = sA[grp][dy][wf + dx];
#pragma unroll
            for (int j = 0; j < 8; j++) {
                float s = acc[j];
#pragma unroll
                for (int dy = 0; dy < 3; dy++)
#pragma unroll
                    for (int dx = 0; dx < 3; dx++) s += sW[grp][j][dy * 3 + dx] * a[dy][dx];
                acc[j] = s;
            }
        }
    }
    __syncthreads();
#pragma unroll
    for (int j = 0; j < 8; j++) sred[grp][j][w] = acc[j];
    __syncthreads();
    if (grp == 0) {
#pragma unroll
        for (int j = 0; j < 8; j++) {
            float tot = sred[0][j][w] + sred[1][j][w] + sred[2][j][w] + sred[3][j][w];
            g_vs[b][cg * 8 + j][w] = 0.25f * tot + 64.f * vb[cg * 8 + j];
        }
    }
}

// G: stage contiguous 2304-float weight block in smem. grid (CE, BB), 64 threads
__global__ void G_kernel(const float* __restrict__ fw) {
    __shared__ float sw[2304];
    int b = blockIdx.y, o = blockIdx.x, t = threadIdx.x;
    const float* wbase = fw + ((size_t)o * FIN + 240) * 9;
    for (int i = t; i < 2304; i += 64) sw[i] = wbase[i];
    __syncthreads();
    float acc[9];
#pragma unroll
    for (int j = 0; j < 9; j++) acc[j] = 0.f;
    for (int c = 0; c < CC; c++) {
        float v = g_vs[b][c][t];
#pragma unroll
        for (int j = 0; j < 9; j++) acc[j] += sw[c * 9 + j] * v;
    }
#pragma unroll
    for (int j = 0; j < 9; j++) g_G[b][o][j][t] = acc[j];
}

// ================= fused split + pool + passthrough =================
// One full read of bev produces: X4 (fp16 channel-last, ch>=16), g_pool (2x2 avg,
// all 256 ch), and the ch0..15 output passthrough.  grid (64 row-pairs, 8 b).
#define SPCB 32
__global__ void __launch_bounds__(256) split_pool_kernel(const float* __restrict__ bev,
                                                         float* __restrict__ out) {
    __shared__ float sb[2][SPCB][130];
    int hp = blockIdx.x, b = blockIdx.y, t = threadIdx.x;
    int y0 = 2 * hp;
    for (int cb = 0; cb < 8; cb++) {
        __syncthreads();
        // load 2 rows x 32 ch x 128 px (2048 float4; 8 per thread)
        for (int i = t; i < 2048; i += 256) {
            int ci = i >> 6;            // 0..31
            int rem = i & 63;
            int row = rem >> 5;
            int x4 = rem & 31;
            int ch = cb * SPCB + ci;
            float4 v = *((const float4*)(bev + (((size_t)b * CC + ch) * HH + y0 + row) * WW) + x4);
            float* d = &sb[row][ci][x4 * 4];
            d[0] = v.x; d[1] = v.y; d[2] = v.z; d[3] = v.w;
        }
        __syncthreads();
        // X4 fp16 packed writes for ch >= 16 (pairs along channel)
        for (int i = t; i < 2 * 128 * 16; i += 256) {
            int row = i >> 11;
            int rem = i & 2047;
            int x = rem >> 4;
            int cp = rem & 15;
            int ch0 = cb * SPCB + 2 * cp;
            if (ch0 >= 16) {
                __half h0 = __float2half(sb[row][2 * cp][x]);
                __half h1 = __float2half(sb[row][2 * cp + 1][x]);
                uint32_t pk = ((uint32_t)__half_as_ushort(h1) << 16) | __half_as_ushort(h0);
                size_t base = (((size_t)b * 128 + y0 + row) * 128 + x) * 128 + (size_t)((ch0 - 16) >> 1);
                ((uint32_t*)g_X4)[base] = pk;
            }
        }
        // 2x2 pooled fp32 (all channels)
        for (int i = t; i < SPCB * 64; i += 256) {
            int ci = i >> 6;
            int w = i & 63;
            int ch = cb * SPCB + ci;
            float m = 0.25f * (sb[0][ci][2 * w] + sb[0][ci][2 * w + 1]
                             + sb[1][ci][2 * w] + sb[1][ci][2 * w + 1]);
            g_pool[b][ch][hp][w] = m;
        }
        // output passthrough for ch 0..15
        if (cb == 0) {
            for (int i = t; i < 16 * 2 * 32; i += 256) {
                int ci = i >> 6;        // 0..15
                int rem = i & 63;
                int row = rem >> 5;
                int x4 = rem & 31;
                const float* s = &sb[row][ci][x4 * 4];
                float4 v;
                v.x = s[0]; v.y = s[1]; v.z = s[2]; v.w = s[3];
                *((float4*)(out + (((size_t)b * CC + ci) * HH + y0 + row) * WW) + x4) = v;
            }
        }
    }
}

__global__ void wbuild_kernel(const float* __restrict__ fw) {
    int tile = blockIdx.y;
    int s = tile >> 2, cib = tile & 3;
    int idx = blockIdx.x * 256 + threadIdx.x;
    int n = idx >> 6, k = idx & 63;
    int ci = cib * 64 + k;
    float v = 0.f;
    if (n < 240 && ci < 240) v = fw[((size_t)n * FIN + ci) * 9 + s];
    ((__half*)(g_W4 + (size_t)tile * 2048))[idx] = __float2half(v);
}

// ================= HMMA conv kernel (R12/R14 config: NCHUNK=36, ROWB=144) =================
#define NCHUNK 36
#define ROWB   144
#define ABYTES (128 * ROWB)
#define BUFSZ  (ABYTES + 256 * ROWB)
#define CONV_SMEM (2 * BUFSZ)

__device__ __forceinline__ void load_chunk(int c, uint32_t sbuf, int t, int b, int y) {
    int s = c >> 2, cib = c & 3;
    int dy = s / 3, dx = s % 3;
    const uint4* Wsrc = g_W4 + (size_t)c * 2048;

    int yy = y + dy - 1;
    bool yok = ((unsigned)yy < 128u);
    const uint4* xrow = g_X4 + (((size_t)b * 128 + (yok ? yy : 0)) * 128) * 32 + cib * 8;
#pragma unroll
    for (int r = 0; r < 2; r++) {
        int i = t + r * 512;
        int m = i >> 3, j = i & 7;
        int xx = m + dx - 1;
        bool ok = yok && ((unsigned)xx < 128u);
        const uint4* src = xrow + (size_t)(ok ? xx : 0) * 32 + j;
        cpasync16(sbuf + m * ROWB + j * 16, src, ok ? 16u : 0u);
    }
#pragma unroll
    for (int r = 0; r < 4; r++) {
        int i = t + r * 512;
        int n = i >> 3, j = i & 7;
        cpasync16(sbuf + ABYTES + n * ROWB + j * 16, Wsrc + n * 8 + j, 16u);
    }
    CP_COMMIT();
}

__device__ __forceinline__ void do_ks(int ks, uint32_t aBase, uint32_t bBase,
                                      float acc[2][8][4], int ntMax, int nnMax) {
    uint32_t a[2][4];
    ldsm4(a[0], aBase + ks * 32);
    ldsm4(a[1], aBase + 16 * ROWB + ks * 32);
    uint32_t bf[4][4];
#pragma unroll
    for (int nt = 0; nt < 4; nt++)
        if (nt < ntMax) ldsm4(bf[nt], bBase + nt * 16 * ROWB + ks * 32);
#pragma unroll
    for (int mt = 0; mt < 2; mt++)
#pragma unroll
        for (int nn = 0; nn < 8; nn++)
            if (nn < nnMax) mma_fp16(acc[mt][nn], a[mt], &bf[nn >> 1][(nn & 1) * 2]);
}

__global__ void __launch_bounds__(512, 1)
mma_conv_kernel(const float* __restrict__ fb, float* __restrict__ out) {
    extern __shared__ uint4 dsm[];
    uint32_t sb = smem_to_u32(dsm);

    int t = threadIdx.x;
    int l = t & 31, wid = t >> 5;
    int y = blockIdx.x, b = blockIdx.y;
    int m0 = (wid & 3) * 32;
    int n0 = (wid >> 2) * 64;
    const int nnMax = (n0 == 192) ? 6 : 8;
    const int ntMax = (n0 == 192) ? 3 : 4;

    float acc[2][8][4];
#pragma unroll
    for (int i = 0; i < 2; i++)
#pragma unroll
        for (int j = 0; j < 8; j++)
#pragma unroll
            for (int k = 0; k < 4; k++) acc[i][j][k] = 0.f;

    uint32_t aOff = (uint32_t)(m0 + (l & 15)) * ROWB + (l >> 4) * 16;
    uint32_t bOff = ABYTES + (uint32_t)(n0 + (l & 7) + ((l >> 4) << 3)) * ROWB
                    + ((l >> 3) & 1) * 16;

    load_chunk(0, sb, t, b, y);
    CP_WAIT0();
    __syncthreads();

    for (int c = 0; c < NCHUNK; c++) {
        uint32_t buf = sb + (c & 1) * BUFSZ;
        if (c + 1 < NCHUNK) load_chunk(c + 1, sb + ((c + 1) & 1) * BUFSZ, t, b, y);

        uint32_t aBase = buf + aOff;
        uint32_t bBase = buf + bOff;
        int ksMax = ((c & 3) == 3) ? 3 : 4;
#pragma unroll
        for (int ks = 0; ks < 4; ks++)
            if (ks < ksMax) do_ks(ks, aBase, bBase, acc, ntMax, nnMax);

        if (c + 1 < NCHUNK) CP_WAIT0();
        __syncthreads();
    }

    // Epilogue: bias + factorized T contribution, scattered stores
    int g = l >> 2, tq = l & 3;
    float* outb = out + ((size_t)b * CC + 16) * (HH * WW) + y * WW;
#pragma unroll
    for (int mt = 0; mt < 2; mt++) {
        int xA = m0 + mt * 16 + g;
        int xB = xA + 8;
#pragma unroll
        for (int nn = 0; nn < 8; nn++) {
            int o0 = n0 + nn * 8 + 2 * tq;
            if (o0 >= 240) continue;
            float b0 = fb[o0], b1 = fb[o0 + 1];
#pragma unroll
            for (int half = 0; half < 2; half++) {
                int x = half ? xB : xA;
                float v0 = acc[mt][nn][half * 2 + 0] + b0;
                float v1 = acc[mt][nn][half * 2 + 1] + b1;
#pragma unroll
                for (int dy2 = 0; dy2 < 3; dy2++) {
                    int yy = y + dy2 - 1;
                    if ((unsigned)yy >= 128u) continue;
                    int hh = yy >> 1;
#pragma unroll
                    for (int dx2 = 0; dx2 < 3; dx2++) {
                        int xx = x + dx2 - 1;
                        if ((unsigned)xx >= 128u) continue;
                        int ww = xx >> 1;
                        float ev = g_e[b][hh][ww];
                        v0 += ev * g_G[b][o0][dy2 * 3 + dx2][ww];
                        v1 += ev * g_G[b][o0 + 1][dy2 * 3 + dx2][ww];
                    }
                }
                outb[(size_t)o0 * (HH * WW) + x] = v0;
                outb[(size_t)(o0 + 1) * (HH * WW) + x] = v1;
            }
        }
    }
}

// ---------------------------------------------------------------
extern "C" void kernel_launch(void* const* d_in, const int* in_sizes, int n_in,
                              void* d_out, int out_size) {
    const float* front = (const float*)d_in[0];
    const float* bev   = (const float*)d_in[1];
    const float* qw    = (const float*)d_in[2];
    const float* qb    = (const float*)d_in[3];
    const float* kw    = (const float*)d_in[4];
    const float* kb    = (const float*)d_in[5];
    const float* vw    = (const float*)d_in[6];
    const float* vb    = (const float*)d_in[7];
    const float* fw    = (const float*)d_in[8];
    const float* fb    = (const float*)d_in[9];
    float* out = (float*)d_out;

    cudaFuncSetAttribute(mma_conv_kernel,
                         cudaFuncAttributeMaxDynamicSharedMemorySize, CONV_SMEM);

    split_pool_kernel<<<dim3(64, BB), 256>>>(bev, out);
    wbuild_kernel<<<dim3(64, 36), 256>>>(fw);
    front_reduce_kernel<<<dim3(CC, BB), 128>>>(front);
    k_kernel<<<dim3(NC8, BB), 256>>>(kw, kb);
    kq_kernel<<<512, 256>>>(qw, qb);
    e_fused_kernel<<<dim3(HP, BB), 256>>>();
    enorm_kernel<<<dim3(WP, BB), HP>>>();
    vsum_kernel<<<dim3(32, BB), 256>>>(vw, vb);
    G_kernel<<<dim3(CE, BB), 64>>>(fw);
    mma_conv_kernel<<<dim3(128, BB), 512, CONV_SMEM>>>(fb, out);
}